// round 4
// baseline (speedup 1.0000x reference)
#include <cuda_runtime.h>
#include <cstdint>

// Problem constants (SemLevelGAT): N=100000 nodes, D=128 feat/out, E=1.6M edges.
#define D_FEAT 128
#define MAX_NODES 100000

// Scratch: aggregated neighbor sums msg[n][d]. Zero-init __device__ global
// (.bss — no runtime allocation, allowed by harness rules).
__device__ float g_msg[(size_t)MAX_NODES * D_FEAT];

// ---------------------------------------------------------------------------
// Kernel 1: zero the msg buffer (graph replays reuse it, so every launch).
// ---------------------------------------------------------------------------
__global__ void zero_msg_kernel(int n4) {
    int i = blockIdx.x * blockDim.x + threadIdx.x;
    if (i < n4) {
        reinterpret_cast<float4*>(g_msg)[i] = make_float4(0.f, 0.f, 0.f, 0.f);
    }
}

// ---------------------------------------------------------------------------
// Kernel 2: edge scatter-add. One warp per edge; lane c handles float4 chunk c.
// msg[dst] += h[src] via red.global.add.v4.f32 (fire-and-forget vector
// reduction, no return trip). h row read = one coalesced 512B transaction per
// warp; src/dst loads are warp-uniform broadcasts.
// NOTE: src/dst are int32 on device (JAX downcasts int64 without x64 mode;
// round-2 fault is only explicable by int32 data read as 64-bit).
// ---------------------------------------------------------------------------
__global__ void scatter_kernel(const float4* __restrict__ h4,
                               const int* __restrict__ src,
                               const int* __restrict__ dst,
                               int E, int M) {
    long long g = (long long)blockIdx.x * blockDim.x + threadIdx.x;
    int e = (int)(g >> 5);
    int c = (int)(g & 31);
    if (e >= E) return;
    int s = __ldg(&src[e]);
    int d = __ldg(&dst[e]);
    // Defensive: never fault on unexpected index contents — wrong dtype would
    // surface as rel_err, not an illegal access that blinds profiling.
    if ((unsigned)s >= (unsigned)M || (unsigned)d >= (unsigned)M) return;
    float4 v = __ldg(&h4[(size_t)s * 32 + c]);
    float* p = &g_msg[((size_t)d << 7) + (c << 2)];
    asm volatile("red.global.add.v4.f32 [%0], {%1,%2,%3,%4};"
                 :: "l"(p), "f"(v.x), "f"(v.y), "f"(v.z), "f"(v.w)
                 : "memory");
}

// ---------------------------------------------------------------------------
// Kernel 3: out[M,128] = msg[M,128] @ W^T, W given as [out(128), in(128)]
// row-major. Tile: 128x128 per block, BK=32, 256 threads, 8x8 micro-tile.
// Smem tiles stored transposed ([k][r], [k][o]) with stride-132 padding:
//   - compute-phase float4 reads along r/o for fixed k: conflict-free
//   - transpose stores: 4-way conflict (tiny fraction of total work)
// ---------------------------------------------------------------------------
#define SST 132   // smem row stride in floats: 16B-aligned, gcd(132,32)=4

__global__ __launch_bounds__(256) void gemm_kernel(const float* __restrict__ W,
                                                   float* __restrict__ out,
                                                   int M) {
    __shared__ float At[32 * SST];  // At[kk][r]
    __shared__ float Wt[32 * SST];  // Wt[kk][o]

    const int tid = threadIdx.x;
    const int rowbase = blockIdx.x * 128;
    const int tx = tid & 15;   // output-col group
    const int ty = tid >> 4;   // output-row group

    float acc[8][8];
#pragma unroll
    for (int i = 0; i < 8; i++)
#pragma unroll
        for (int j = 0; j < 8; j++) acc[i][j] = 0.f;

    for (int kb = 0; kb < 128; kb += 32) {
        __syncthreads();
        // 4096 elements each of A and W per chunk, 16 per thread.
        // Within a warp: r constant, kk = lane -> 128B coalesced global reads.
#pragma unroll
        for (int t = 0; t < 16; t++) {
            int i  = tid + t * 256;
            int r  = i >> 5;
            int kk = i & 31;
            int row = rowbase + r;
            At[kk * SST + r] = (row < M)
                ? g_msg[((size_t)row << 7) + kb + kk] : 0.f;
            Wt[kk * SST + r] = __ldg(&W[((size_t)r << 7) + kb + kk]);
        }
        __syncthreads();

#pragma unroll 4
        for (int kk = 0; kk < 32; kk++) {
            float4 a0 = *reinterpret_cast<const float4*>(&At[kk * SST + ty * 4]);
            float4 a1 = *reinterpret_cast<const float4*>(&At[kk * SST + 64 + ty * 4]);
            float4 b0 = *reinterpret_cast<const float4*>(&Wt[kk * SST + tx * 4]);
            float4 b1 = *reinterpret_cast<const float4*>(&Wt[kk * SST + 64 + tx * 4]);
            float a[8] = {a0.x, a0.y, a0.z, a0.w, a1.x, a1.y, a1.z, a1.w};
            float b[8] = {b0.x, b0.y, b0.z, b0.w, b1.x, b1.y, b1.z, b1.w};
#pragma unroll
            for (int i = 0; i < 8; i++)
#pragma unroll
                for (int j = 0; j < 8; j++)
                    acc[i][j] += a[i] * b[j];
        }
    }

#pragma unroll
    for (int i = 0; i < 8; i++) {
        int r = rowbase + ((i < 4) ? (ty * 4 + i) : (64 + ty * 4 + i - 4));
        if (r < M) {
            float4 v0 = make_float4(acc[i][0], acc[i][1], acc[i][2], acc[i][3]);
            float4 v1 = make_float4(acc[i][4], acc[i][5], acc[i][6], acc[i][7]);
            *reinterpret_cast<float4*>(&out[((size_t)r << 7) + tx * 4]) = v0;
            *reinterpret_cast<float4*>(&out[((size_t)r << 7) + 64 + tx * 4]) = v1;
        }
    }
}

// ---------------------------------------------------------------------------
// Launch. Inputs (metadata order): h f32[N*128], edge_types f32[E*8],
// w_attn f32[8], W_lin f32[128*128], src i32[E], dst i32[E].
// Softmax over a size-1 axis is identically 1.0 => edge_types/w_attn are dead:
//   out = segment_sum(h[src], dst) @ W_lin^T
// ---------------------------------------------------------------------------
extern "C" void kernel_launch(void* const* d_in, const int* in_sizes, int n_in,
                              void* d_out, int out_size) {
    const float* h    = (const float*)d_in[0];
    const float* Wlin = (const float*)d_in[3];
    const int*   src  = (const int*)d_in[4];
    const int*   dst  = (const int*)d_in[5];
    float* out = (float*)d_out;

    int M = in_sizes[0] / D_FEAT;           // 100000
    if (M > MAX_NODES) M = MAX_NODES;       // scratch bound
    int E = in_sizes[4];                    // 1600000

    // 1) zero msg
    int n4 = M * (D_FEAT / 4);
    zero_msg_kernel<<<(n4 + 255) / 256, 256>>>(n4);

    // 2) scatter-add h[src] into msg[dst]
    long long threads = (long long)E * 32;
    unsigned blocks = (unsigned)((threads + 255) / 256);
    scatter_kernel<<<blocks, 256>>>((const float4*)h, src, dst, E, M);

    // 3) out = msg @ W^T
    gemm_kernel<<<(M + 127) / 128, 256>>>(Wlin, out, M);
}

// round 5
// speedup vs baseline: 1.4585x; 1.4585x over previous
#include <cuda_runtime.h>
#include <cstdint>

// SemLevelGAT: N=100000 nodes, D=128, E=1.6M edges.
// out = segment_sum(h[src], dst) @ W_lin^T   (softmax over size-1 axis == 1)
#define D_FEAT 128
#define MAX_NODES 100000
#define MAX_EDGES 1600000
#define SCAN_B 1024
#define NSCAN ((MAX_NODES + SCAN_B - 1) / SCAN_B)   // 98

// Scratch (__device__ globals: module-load allocation, allowed).
__device__ float g_msg[(size_t)MAX_NODES * D_FEAT];   // aggregated rows
__device__ int   g_deg[MAX_NODES];                    // histogram (degrees)
__device__ int   g_base[MAX_NODES];                   // exclusive scan of deg
__device__ int   g_cur[MAX_NODES];                    // bin cursors
__device__ int   g_bsum[128];                         // per-scan-block sums
__device__ int   g_boff[128];                         // scanned block sums
__device__ int   g_esrc[MAX_EDGES];                   // src ids binned by dst

// ---------------------------------------------------------------------------
// 1) zero degree histogram (graph replays reuse scratch -> every launch)
// ---------------------------------------------------------------------------
__global__ void zero_deg_kernel(int M) {
    int i = blockIdx.x * blockDim.x + threadIdx.x;
    if (i < M) g_deg[i] = 0;
}

// ---------------------------------------------------------------------------
// 2) histogram of dst
// ---------------------------------------------------------------------------
__global__ void hist_kernel(const int* __restrict__ dst,
                            const int* __restrict__ src, int E, int M) {
    int e = blockIdx.x * blockDim.x + threadIdx.x;
    if (e >= E) return;
    int d = __ldg(&dst[e]);
    int s = __ldg(&src[e]);
    if ((unsigned)d >= (unsigned)M || (unsigned)s >= (unsigned)M) return;
    atomicAdd(&g_deg[d], 1);
}

// ---------------------------------------------------------------------------
// 3a) per-block inclusive scan of deg -> exclusive per-element, block totals
// ---------------------------------------------------------------------------
__global__ void scan1_kernel(int M) {
    __shared__ int sh[SCAN_B];
    int t = threadIdx.x;
    int i = blockIdx.x * SCAN_B + t;
    int v = (i < M) ? g_deg[i] : 0;
    sh[t] = v;
#pragma unroll
    for (int off = 1; off < SCAN_B; off <<= 1) {
        __syncthreads();
        int x = (t >= off) ? sh[t - off] : 0;
        __syncthreads();
        sh[t] += x;
    }
    __syncthreads();
    if (i < M) g_base[i] = sh[t] - v;       // exclusive
    if (t == SCAN_B - 1) g_bsum[blockIdx.x] = sh[t];
}

// ---------------------------------------------------------------------------
// 3b) scan the (<=128) block sums in one block
// ---------------------------------------------------------------------------
__global__ void scan2_kernel(int nb) {
    __shared__ int sh[128];
    int t = threadIdx.x;
    int v = (t < nb) ? g_bsum[t] : 0;
    sh[t] = v;
#pragma unroll
    for (int off = 1; off < 128; off <<= 1) {
        __syncthreads();
        int x = (t >= off) ? sh[t - off] : 0;
        __syncthreads();
        sh[t] += x;
    }
    __syncthreads();
    if (t < nb) g_boff[t] = sh[t] - v;      // exclusive
}

// ---------------------------------------------------------------------------
// 3c) add block offsets; init cursors
// ---------------------------------------------------------------------------
__global__ void scan3_kernel(int M) {
    int i = blockIdx.x * blockDim.x + threadIdx.x;
    if (i >= M) return;
    int b = g_base[i] + g_boff[i >> 10];
    g_base[i] = b;
    g_cur[i]  = b;
}

// ---------------------------------------------------------------------------
// 4) bin src ids by dst
// ---------------------------------------------------------------------------
__global__ void bin_kernel(const int* __restrict__ dst,
                           const int* __restrict__ src, int E, int M) {
    int e = blockIdx.x * blockDim.x + threadIdx.x;
    if (e >= E) return;
    int d = __ldg(&dst[e]);
    int s = __ldg(&src[e]);
    if ((unsigned)d >= (unsigned)M || (unsigned)s >= (unsigned)M) return;
    int pos = atomicAdd(&g_cur[d], 1);
    g_esrc[pos] = s;
}

// ---------------------------------------------------------------------------
// 5) gather: one warp per dst node. Lane c accumulates float4 chunk c of the
// row in a register; edge indices prefetched 32-wide and shfl-broadcast so
// the inner loop has no dependent scalar load. Writes EVERY row (no zeroing
// of msg needed anywhere).
// ---------------------------------------------------------------------------
__global__ void gather_kernel(const float4* __restrict__ h4, int M) {
    int w = (blockIdx.x * blockDim.x + threadIdx.x) >> 5;
    int lane = threadIdx.x & 31;
    if (w >= M) return;
    int beg = __ldg(&g_base[w]);
    int deg = __ldg(&g_deg[w]);
    float4 acc = make_float4(0.f, 0.f, 0.f, 0.f);
    for (int c0 = 0; c0 < deg; c0 += 32) {
        int n = min(32, deg - c0);
        int idx = (lane < n) ? __ldg(&g_esrc[beg + c0 + lane]) : 0;
        for (int j = 0; j < n; j++) {
            int s = __shfl_sync(0xFFFFFFFFu, idx, j);
            float4 v = __ldg(&h4[(size_t)s * 32 + lane]);
            acc.x += v.x; acc.y += v.y; acc.z += v.z; acc.w += v.w;
        }
    }
    reinterpret_cast<float4*>(g_msg)[(size_t)w * 32 + lane] = acc;
}

// ---------------------------------------------------------------------------
// 6) out[M,128] = msg @ W^T. 128x128 tile, BK=32, 256 thr, 8x8 micro-tile.
// ---------------------------------------------------------------------------
#define SST 132

__global__ __launch_bounds__(256) void gemm_kernel(const float* __restrict__ W,
                                                   float* __restrict__ out,
                                                   int M) {
    __shared__ float At[32 * SST];
    __shared__ float Wt[32 * SST];

    const int tid = threadIdx.x;
    const int rowbase = blockIdx.x * 128;
    const int tx = tid & 15;
    const int ty = tid >> 4;

    float acc[8][8];
#pragma unroll
    for (int i = 0; i < 8; i++)
#pragma unroll
        for (int j = 0; j < 8; j++) acc[i][j] = 0.f;

    for (int kb = 0; kb < 128; kb += 32) {
        __syncthreads();
#pragma unroll
        for (int t = 0; t < 16; t++) {
            int i  = tid + t * 256;
            int r  = i >> 5;
            int kk = i & 31;
            int row = rowbase + r;
            At[kk * SST + r] = (row < M)
                ? g_msg[((size_t)row << 7) + kb + kk] : 0.f;
            Wt[kk * SST + r] = __ldg(&W[((size_t)r << 7) + kb + kk]);
        }
        __syncthreads();

#pragma unroll 4
        for (int kk = 0; kk < 32; kk++) {
            float4 a0 = *reinterpret_cast<const float4*>(&At[kk * SST + ty * 4]);
            float4 a1 = *reinterpret_cast<const float4*>(&At[kk * SST + 64 + ty * 4]);
            float4 b0 = *reinterpret_cast<const float4*>(&Wt[kk * SST + tx * 4]);
            float4 b1 = *reinterpret_cast<const float4*>(&Wt[kk * SST + 64 + tx * 4]);
            float a[8] = {a0.x, a0.y, a0.z, a0.w, a1.x, a1.y, a1.z, a1.w};
            float b[8] = {b0.x, b0.y, b0.z, b0.w, b1.x, b1.y, b1.z, b1.w};
#pragma unroll
            for (int i = 0; i < 8; i++)
#pragma unroll
                for (int j = 0; j < 8; j++)
                    acc[i][j] += a[i] * b[j];
        }
    }

#pragma unroll
    for (int i = 0; i < 8; i++) {
        int r = rowbase + ((i < 4) ? (ty * 4 + i) : (64 + ty * 4 + i - 4));
        if (r < M) {
            float4 v0 = make_float4(acc[i][0], acc[i][1], acc[i][2], acc[i][3]);
            float4 v1 = make_float4(acc[i][4], acc[i][5], acc[i][6], acc[i][7]);
            *reinterpret_cast<float4*>(&out[((size_t)r << 7) + tx * 4]) = v0;
            *reinterpret_cast<float4*>(&out[((size_t)r << 7) + 64 + tx * 4]) = v1;
        }
    }
}

// ---------------------------------------------------------------------------
// Launch. Inputs: h f32[N*128], edge_types f32[E*8], w_attn f32[8],
// W_lin f32[128*128], src i32[E], dst i32[E].
// ---------------------------------------------------------------------------
extern "C" void kernel_launch(void* const* d_in, const int* in_sizes, int n_in,
                              void* d_out, int out_size) {
    const float* h    = (const float*)d_in[0];
    const float* Wlin = (const float*)d_in[3];
    const int*   src  = (const int*)d_in[4];
    const int*   dst  = (const int*)d_in[5];
    float* out = (float*)d_out;

    int M = in_sizes[0] / D_FEAT;
    if (M > MAX_NODES) M = MAX_NODES;
    int E = in_sizes[4];
    if (E > MAX_EDGES) E = MAX_EDGES;

    int nb = (M + SCAN_B - 1) / SCAN_B;     // <= 98

    zero_deg_kernel<<<(M + 255) / 256, 256>>>(M);
    hist_kernel<<<(E + 255) / 256, 256>>>(dst, src, E, M);
    scan1_kernel<<<nb, SCAN_B>>>(M);
    scan2_kernel<<<1, 128>>>(nb);
    scan3_kernel<<<(M + 255) / 256, 256>>>(M);
    bin_kernel<<<(E + 255) / 256, 256>>>(dst, src, E, M);

    long long gthreads = (long long)M * 32;
    gather_kernel<<<(unsigned)((gthreads + 255) / 256), 256>>>((const float4*)h, M);

    gemm_kernel<<<(M + 127) / 128, 256>>>(Wlin, out, M);
}

// round 6
// speedup vs baseline: 2.0356x; 1.3957x over previous
#include <cuda_runtime.h>
#include <cuda_bf16.h>
#include <cstdint>

// SemLevelGAT: N=100000 nodes, D=128, E=1.6M edges.
// out = segment_sum(h[src], dst) @ W_lin^T   (softmax over size-1 axis == 1)
#define D_FEAT 128
#define MAX_NODES 100000
#define MAX_EDGES 1600000
#define SCAN_B 1024

// Scratch (__device__ globals: module-load allocation, allowed).
__device__ float g_msg[(size_t)MAX_NODES * D_FEAT];   // aggregated rows
__device__ int   g_deg[MAX_NODES];                    // degree histogram
__device__ int   g_base[MAX_NODES];                   // CSR row starts
__device__ int   g_cur[MAX_NODES];                    // bin cursors
__device__ int   g_bsum[128];                         // scan block sums
__device__ int   g_esrc[MAX_EDGES];                   // src ids binned by dst
__device__ __nv_bfloat16 g_Whi[D_FEAT * D_FEAT];      // W split hi
__device__ __nv_bfloat16 g_Wlo[D_FEAT * D_FEAT];      // W split lo

// ---------------------------------------------------------------------------
// 1) zero degree histogram + split W into bf16 hi/lo (fused, one launch)
// ---------------------------------------------------------------------------
__global__ void prep_kernel(const float* __restrict__ W, int M) {
    int i = blockIdx.x * blockDim.x + threadIdx.x;
    if (i < M) g_deg[i] = 0;
    if (i < D_FEAT * D_FEAT) {
        float w = __ldg(&W[i]);
        __nv_bfloat16 hi = __float2bfloat16(w);
        g_Whi[i] = hi;
        g_Wlo[i] = __float2bfloat16(w - __bfloat162float(hi));
    }
}

// ---------------------------------------------------------------------------
// 2) histogram of dst
// ---------------------------------------------------------------------------
__global__ void hist_kernel(const int* __restrict__ dst,
                            const int* __restrict__ src, int E, int M) {
    int e = blockIdx.x * blockDim.x + threadIdx.x;
    if (e >= E) return;
    int d = __ldg(&dst[e]);
    int s = __ldg(&src[e]);
    if ((unsigned)d >= (unsigned)M || (unsigned)s >= (unsigned)M) return;
    atomicAdd(&g_deg[d], 1);
}

// ---------------------------------------------------------------------------
// 3a) per-block scan of deg -> exclusive per-element g_base, block totals
// ---------------------------------------------------------------------------
__global__ void scan1_kernel(int M) {
    __shared__ int sh[SCAN_B];
    int t = threadIdx.x;
    int i = blockIdx.x * SCAN_B + t;
    int v = (i < M) ? g_deg[i] : 0;
    sh[t] = v;
#pragma unroll
    for (int off = 1; off < SCAN_B; off <<= 1) {
        __syncthreads();
        int x = (t >= off) ? sh[t - off] : 0;
        __syncthreads();
        sh[t] += x;
    }
    __syncthreads();
    if (i < M) g_base[i] = sh[t] - v;       // exclusive within block
    if (t == SCAN_B - 1) g_bsum[blockIdx.x] = sh[t];
}

// ---------------------------------------------------------------------------
// 3b) add block offsets (each block re-scans the <=128 block sums in smem —
//     cheaper than a separate 1-block kernel launch); init cursors
// ---------------------------------------------------------------------------
__global__ void scan3_kernel(int M, int nb) {
    __shared__ int sh[128];
    int t = threadIdx.x;
    if (t < 128) sh[t] = (t < nb) ? g_bsum[t] : 0;
#pragma unroll
    for (int off = 1; off < 128; off <<= 1) {
        __syncthreads();
        int x = (t >= off && t < 128) ? sh[t - off] : 0;
        __syncthreads();
        if (t < 128) sh[t] += x;             // inclusive scan of block sums
    }
    __syncthreads();
    int i = blockIdx.x * blockDim.x + t;
    if (i < M) {
        int sb = i >> 10;
        int b = g_base[i] + ((sb == 0) ? 0 : sh[sb - 1]);
        g_base[i] = b;
        g_cur[i]  = b;
    }
}

// ---------------------------------------------------------------------------
// 4) bin src ids by dst
// ---------------------------------------------------------------------------
__global__ void bin_kernel(const int* __restrict__ dst,
                           const int* __restrict__ src, int E, int M) {
    int e = blockIdx.x * blockDim.x + threadIdx.x;
    if (e >= E) return;
    int d = __ldg(&dst[e]);
    int s = __ldg(&src[e]);
    if ((unsigned)d >= (unsigned)M || (unsigned)s >= (unsigned)M) return;
    int pos = atomicAdd(&g_cur[d], 1);
    g_esrc[pos] = s;
}

// ---------------------------------------------------------------------------
// 5) gather: one warp per dst node; lane c owns float4 chunk c. Edge ids
// prefetched 32-wide + shfl-broadcast. Writes every row (no zeroing needed).
// ---------------------------------------------------------------------------
__global__ void gather_kernel(const float4* __restrict__ h4, int M) {
    int w = (blockIdx.x * blockDim.x + threadIdx.x) >> 5;
    int lane = threadIdx.x & 31;
    if (w >= M) return;
    int beg = __ldg(&g_base[w]);
    int deg = __ldg(&g_deg[w]);
    float4 acc = make_float4(0.f, 0.f, 0.f, 0.f);
    for (int c0 = 0; c0 < deg; c0 += 32) {
        int n = min(32, deg - c0);
        int idx = (lane < n) ? __ldg(&g_esrc[beg + c0 + lane]) : 0;
        for (int j = 0; j < n; j++) {
            int s = __shfl_sync(0xFFFFFFFFu, idx, j);
            float4 v = __ldg(&h4[(size_t)s * 32 + lane]);
            acc.x += v.x; acc.y += v.y; acc.z += v.z; acc.w += v.w;
        }
    }
    reinterpret_cast<float4*>(g_msg)[(size_t)w * 32 + lane] = acc;
}

// ---------------------------------------------------------------------------
// 6) out[M,128] = msg @ W^T via split-bf16 tensor-core mma:
//    A = A_hi + A_lo, W = W_hi + W_lo (bf16);  acc += Ahi*Whi + Ahi*Wlo + Alo*Whi
//    (dropped lo*lo term ~2^-18 relative). fp32 accumulate.
// Block: 256 thr (8 warps), tile 128(M)x128(N). Warp = 64x32 region
// (4 m-subtiles x 4 n-subtiles of m16n8k16). K staged in two 64-wide halves;
// A converted fp32->hi/lo during smem staging. B frags read from L1-hot W.
// ---------------------------------------------------------------------------
#define AK 64
#define AST 72   // smem row stride in halves; lane->bank is identity (no conflicts)

__device__ __forceinline__ void mma_bf16(float* c, const unsigned* a, const unsigned* b) {
    asm volatile(
        "mma.sync.aligned.m16n8k16.row.col.f32.bf16.bf16.f32 "
        "{%0,%1,%2,%3}, {%4,%5,%6,%7}, {%8,%9}, {%0,%1,%2,%3};\n"
        : "+f"(c[0]), "+f"(c[1]), "+f"(c[2]), "+f"(c[3])
        : "r"(a[0]), "r"(a[1]), "r"(a[2]), "r"(a[3]), "r"(b[0]), "r"(b[1]));
}

__global__ __launch_bounds__(256) void gemm_bf16_kernel(float* __restrict__ out,
                                                        int M) {
    __shared__ __nv_bfloat16 Ahi[128 * AST];
    __shared__ __nv_bfloat16 Alo[128 * AST];

    const int tid   = threadIdx.x;
    const int lane  = tid & 31;
    const int warp  = tid >> 5;       // 0..7
    const int warpM = warp >> 2;      // 0..1 : m offset 64*warpM
    const int warpN = warp & 3;       // 0..3 : n offset 32*warpN
    const int grp   = lane >> 2;      // groupID 0..7
    const int tig   = lane & 3;       // thread-in-group
    const int rowbase = blockIdx.x * 128;

    float acc[4][4][4];
#pragma unroll
    for (int mi = 0; mi < 4; mi++)
#pragma unroll
        for (int ni = 0; ni < 4; ni++)
#pragma unroll
            for (int c = 0; c < 4; c++) acc[mi][ni][c] = 0.f;

    for (int kh = 0; kh < 2; kh++) {
        __syncthreads();
        // Stage A k-half: 128 rows x 64 cols fp32 -> bf16 hi/lo in smem.
#pragma unroll
        for (int t = 0; t < 8; t++) {
            int fid = tid + t * 256;          // 0..2047 float4 ids (16 per row)
            int r   = fid >> 4;
            int c4  = fid & 15;
            int row = rowbase + r;
            float4 v = (row < M)
                ? *reinterpret_cast<const float4*>(&g_msg[((size_t)row << 7) + kh * 64 + c4 * 4])
                : make_float4(0.f, 0.f, 0.f, 0.f);
            int sb = r * AST + c4 * 4;
            float vv[4] = {v.x, v.y, v.z, v.w};
#pragma unroll
            for (int q = 0; q < 4; q++) {
                __nv_bfloat16 hi = __float2bfloat16(vv[q]);
                Ahi[sb + q] = hi;
                Alo[sb + q] = __float2bfloat16(vv[q] - __bfloat162float(hi));
            }
        }
        __syncthreads();

#pragma unroll
        for (int kk = 0; kk < 4; kk++) {
            int kglob = kh * 64 + kk * 16;
            // B fragments for 4 n-subtiles (hi & lo), straight from global W.
            unsigned bhi[4][2], blo[4][2];
#pragma unroll
            for (int ni = 0; ni < 4; ni++) {
                int n = warpN * 32 + ni * 8 + grp;
                const unsigned* ph = reinterpret_cast<const unsigned*>(&g_Whi[n * 128 + kglob]);
                const unsigned* pl = reinterpret_cast<const unsigned*>(&g_Wlo[n * 128 + kglob]);
                bhi[ni][0] = ph[tig];     bhi[ni][1] = ph[tig + 4];
                blo[ni][0] = pl[tig];     blo[ni][1] = pl[tig + 4];
            }
#pragma unroll
            for (int mi = 0; mi < 4; mi++) {
                int r0   = warpM * 64 + mi * 16 + grp;
                int koff = kk * 16 + 2 * tig;
                unsigned ahi[4], alo[4];
                ahi[0] = *reinterpret_cast<const unsigned*>(&Ahi[r0 * AST + koff]);
                ahi[1] = *reinterpret_cast<const unsigned*>(&Ahi[(r0 + 8) * AST + koff]);
                ahi[2] = *reinterpret_cast<const unsigned*>(&Ahi[r0 * AST + koff + 8]);
                ahi[3] = *reinterpret_cast<const unsigned*>(&Ahi[(r0 + 8) * AST + koff + 8]);
                alo[0] = *reinterpret_cast<const unsigned*>(&Alo[r0 * AST + koff]);
                alo[1] = *reinterpret_cast<const unsigned*>(&Alo[(r0 + 8) * AST + koff]);
                alo[2] = *reinterpret_cast<const unsigned*>(&Alo[r0 * AST + koff + 8]);
                alo[3] = *reinterpret_cast<const unsigned*>(&Alo[(r0 + 8) * AST + koff + 8]);
#pragma unroll
                for (int ni = 0; ni < 4; ni++) {
                    mma_bf16(acc[mi][ni], ahi, bhi[ni]);
                    mma_bf16(acc[mi][ni], ahi, blo[ni]);
                    mma_bf16(acc[mi][ni], alo, bhi[ni]);
                }
            }
        }
    }

    // Epilogue: c0,c1 = (row grp, cols 2*tig,2*tig+1); c2,c3 = row grp+8.
#pragma unroll
    for (int mi = 0; mi < 4; mi++) {
#pragma unroll
        for (int ni = 0; ni < 4; ni++) {
            int col  = warpN * 32 + ni * 8 + tig * 2;
            int row0 = rowbase + warpM * 64 + mi * 16 + grp;
            if (row0 < M) {
                float2 v = make_float2(acc[mi][ni][0], acc[mi][ni][1]);
                *reinterpret_cast<float2*>(&out[((size_t)row0 << 7) + col]) = v;
            }
            int row1 = row0 + 8;
            if (row1 < M) {
                float2 v = make_float2(acc[mi][ni][2], acc[mi][ni][3]);
                *reinterpret_cast<float2*>(&out[((size_t)row1 << 7) + col]) = v;
            }
        }
    }
}

// ---------------------------------------------------------------------------
// Launch. Inputs: h f32[N*128], edge_types f32[E*8], w_attn f32[8],
// W_lin f32[128*128], src i32[E], dst i32[E].
// ---------------------------------------------------------------------------
extern "C" void kernel_launch(void* const* d_in, const int* in_sizes, int n_in,
                              void* d_out, int out_size) {
    const float* h    = (const float*)d_in[0];
    const float* Wlin = (const float*)d_in[3];
    const int*   src  = (const int*)d_in[4];
    const int*   dst  = (const int*)d_in[5];
    float* out = (float*)d_out;

    int M = in_sizes[0] / D_FEAT;
    if (M > MAX_NODES) M = MAX_NODES;
    int E = in_sizes[4];
    if (E > MAX_EDGES) E = MAX_EDGES;

    int nb = (M + SCAN_B - 1) / SCAN_B;     // <= 98

    prep_kernel<<<(M + 255) / 256, 256>>>(Wlin, M);
    hist_kernel<<<(E + 255) / 256, 256>>>(dst, src, E, M);
    scan1_kernel<<<nb, SCAN_B>>>(M);
    scan3_kernel<<<(M + 255) / 256, 256>>>(M, nb);
    bin_kernel<<<(E + 255) / 256, 256>>>(dst, src, E, M);

    long long gthreads = (long long)M * 32;
    gather_kernel<<<(unsigned)((gthreads + 255) / 256), 256>>>((const float4*)h, M);

    gemm_bf16_kernel<<<(M + 127) / 128, 256>>>(out, M);
}